// round 1
// baseline (speedup 1.0000x reference)
#include <cuda_runtime.h>
#include <cuda_bf16.h>

#define KN   16
#define CIN  64
#define COUT 64
#define DIN  67   // 3 + CIN
#define DPAD 68   // padded to multiple of 4

__device__ int g_idx64;

// Detect whether idx buffer is int64 (high 32-bit words all zero for values < 1e5)
// or int32 (odd positions are random indices, ~never all zero across 2048 samples).
__global__ void detect_idx_kernel(const int* __restrict__ v) {
    __shared__ int s_bad;
    if (threadIdx.x == 0) s_bad = 0;
    __syncthreads();
    int bad = 0;
    for (int i = threadIdx.x; i < 2048; i += blockDim.x)
        if (v[2 * i + 1] != 0) bad = 1;
    if (bad) s_bad = 1;  // benign race, all writers write 1
    __syncthreads();
    if (threadIdx.x == 0) g_idx64 = (s_bad == 0) ? 1 : 0;
}

__global__ __launch_bounds__(256) void gno_kernel(
    const float* __restrict__ coords,
    const float* __restrict__ features,
    const void*  __restrict__ idx,
    const float* __restrict__ W1,
    const float* __restrict__ b1,
    const float* __restrict__ W2,
    const float* __restrict__ b2,
    const float* __restrict__ Ws,
    const float* __restrict__ bs,
    float* __restrict__ out,
    int N)
{
    __shared__ float sW1[DPAD * COUT];   // row i: sW1[i*64 + j], row 67 zeroed
    __shared__ float sW2[COUT * COUT];
    __shared__ float sb1[COUT];
    __shared__ float sin_buf[8][DPAD];   // per-warp staged MLP input
    __shared__ float sh_buf[8][COUT];    // per-warp hidden / scratch

    // Load weights into shared
    for (int t = threadIdx.x; t < DIN * COUT; t += 256)
        sW1[t] = W1[t];
    if (threadIdx.x < COUT) {
        sW1[DIN * COUT + threadIdx.x] = 0.f;   // zero pad row 67
        sb1[threadIdx.x] = b1[threadIdx.x];
    }
    for (int t = threadIdx.x; t < COUT * COUT; t += 256)
        sW2[t] = W2[t];
    __syncthreads();

    const int warp = threadIdx.x >> 5;
    const int lane = threadIdx.x & 31;
    const int j0 = 2 * lane;                     // this thread owns channels j0, j0+1

    const bool is64 = (g_idx64 != 0);
    const long long* idx64 = (const long long*)idx;
    const int*       idx32 = (const int*)idx;

    const int nwarps = gridDim.x * 8;
    for (int n = blockIdx.x * 8 + warp; n < N; n += nwarps) {
        const float cx = coords[3 * n + 0];
        const float cy = coords[3 * n + 1];
        const float cz = coords[3 * n + 2];

        float acc0 = 0.f, acc1 = 0.f;

        for (int k = 0; k < KN; ++k) {
            long long m = is64 ? idx64[(long long)n * KN + k]
                               : (long long)idx32[n * KN + k];
            // Stage input: [relx, rely, relz, feat0..feat63, 0]
            if (lane == 0) {
                sin_buf[warp][0] = coords[3 * m + 0] - cx;
                sin_buf[warp][1] = coords[3 * m + 1] - cy;
                sin_buf[warp][2] = coords[3 * m + 2] - cz;
                sin_buf[warp][DIN] = 0.f;
            }
            float2 f2 = *(const float2*)(features + m * CIN + j0);
            sin_buf[warp][3 + j0]     = f2.x;
            sin_buf[warp][3 + j0 + 1] = f2.y;
            __syncwarp();

            // Hidden layer: h[j] = b1[j] + sum_i in[i] * W1[i][j]
            float h0 = sb1[j0], h1 = sb1[j0 + 1];
            #pragma unroll
            for (int i4 = 0; i4 < DPAD; i4 += 4) {
                float4 x = *(const float4*)(&sin_buf[warp][i4]);
                float2 w;
                w = *(const float2*)(&sW1[(i4 + 0) * COUT + j0]); h0 += x.x * w.x; h1 += x.x * w.y;
                w = *(const float2*)(&sW1[(i4 + 1) * COUT + j0]); h0 += x.y * w.x; h1 += x.y * w.y;
                w = *(const float2*)(&sW1[(i4 + 2) * COUT + j0]); h0 += x.z * w.x; h1 += x.z * w.y;
                w = *(const float2*)(&sW1[(i4 + 3) * COUT + j0]); h0 += x.w * w.x; h1 += x.w * w.y;
            }
            // Exact GELU (erf form, matches torch/jax approximate=False)
            h0 = 0.5f * h0 * (1.f + erff(h0 * 0.70710678118654752f));
            h1 = 0.5f * h1 * (1.f + erff(h1 * 0.70710678118654752f));

            sh_buf[warp][j0]     = h0;
            sh_buf[warp][j0 + 1] = h1;
            __syncwarp();

            // Second layer accumulated across neighbors (b2 folded in at the end)
            #pragma unroll
            for (int jj = 0; jj < COUT; jj += 4) {
                float4 h = *(const float4*)(&sh_buf[warp][jj]);
                float2 w;
                w = *(const float2*)(&sW2[(jj + 0) * COUT + j0]); acc0 += h.x * w.x; acc1 += h.x * w.y;
                w = *(const float2*)(&sW2[(jj + 1) * COUT + j0]); acc0 += h.y * w.x; acc1 += h.y * w.y;
                w = *(const float2*)(&sW2[(jj + 2) * COUT + j0]); acc0 += h.z * w.x; acc1 += h.z * w.y;
                w = *(const float2*)(&sW2[(jj + 3) * COUT + j0]); acc0 += h.w * w.x; acc1 += h.w * w.y;
            }
            __syncwarp();   // before next k overwrites sin_buf/sh_buf
        }

        // mean over K, add b2
        acc0 *= (1.f / KN); acc1 *= (1.f / KN);
        acc0 += b2[j0]; acc1 += b2[j0 + 1];

        // Skip connection: features[n] @ Ws + bs  (Ws via L1 — read-only, cache resident)
        float2 fn = *(const float2*)(features + (long long)n * CIN + j0);
        sh_buf[warp][j0]     = fn.x;
        sh_buf[warp][j0 + 1] = fn.y;
        __syncwarp();
        #pragma unroll
        for (int jj = 0; jj < CIN; jj += 4) {
            float4 f = *(const float4*)(&sh_buf[warp][jj]);
            float2 w;
            w = *(const float2*)(&Ws[(jj + 0) * COUT + j0]); acc0 += f.x * w.x; acc1 += f.x * w.y;
            w = *(const float2*)(&Ws[(jj + 1) * COUT + j0]); acc0 += f.y * w.x; acc1 += f.y * w.y;
            w = *(const float2*)(&Ws[(jj + 2) * COUT + j0]); acc0 += f.z * w.x; acc1 += f.z * w.y;
            w = *(const float2*)(&Ws[(jj + 3) * COUT + j0]); acc0 += f.w * w.x; acc1 += f.w * w.y;
        }
        acc0 += bs[j0]; acc1 += bs[j0 + 1];

        *(float2*)(out + (long long)n * COUT + j0) = make_float2(acc0, acc1);
        __syncwarp();   // before next point's writes to sh_buf
    }
}

extern "C" void kernel_launch(void* const* d_in, const int* in_sizes, int n_in,
                              void* d_out, int out_size) {
    const float* coords   = (const float*)d_in[0];
    const float* features = (const float*)d_in[1];
    const void*  idx      = d_in[2];
    const float* W1 = (const float*)d_in[3];
    const float* b1 = (const float*)d_in[4];
    const float* W2 = (const float*)d_in[5];
    const float* b2 = (const float*)d_in[6];
    const float* Ws = (const float*)d_in[7];
    const float* bs = (const float*)d_in[8];
    float* out = (float*)d_out;

    int N = in_sizes[0] / 3;

    detect_idx_kernel<<<1, 256>>>((const int*)idx);

    int blocks = (N + 7) / 8;   // one warp per point
    gno_kernel<<<blocks, 256>>>(coords, features, idx, W1, b1, W2, b2, Ws, bs, out, N);
}

// round 11
// speedup vs baseline: 6.0737x; 6.0737x over previous
#include <cuda_runtime.h>

#define KN   16
#define CIN  64
#define COUT 64
#define DIN  67              // 3 + CIN
#define NMAX 100000
#define PB   64              // points per block
#define HD   128             // hbar(64) + feat(64)
#define HSTR 132             // sHF row stride in floats (even, padded)
#define XSTR 72              // K1 staging row stride

__device__ int g_idx64;
__device__ float g_A[(size_t)NMAX * COUT];   // A[n][c] = coords[n]@W1pos + feat[n]@W1feat + b1

// ---------------- idx dtype detection (int64 vs int32) ----------------
__global__ void detect_idx_kernel(const int* __restrict__ v) {
    __shared__ int s_bad;
    if (threadIdx.x == 0) s_bad = 0;
    __syncthreads();
    int bad = 0;
    for (int i = threadIdx.x; i < 2048; i += blockDim.x)
        if (v[2 * i + 1] != 0) bad = 1;
    if (bad) s_bad = 1;
    __syncthreads();
    if (threadIdx.x == 0) g_idx64 = (s_bad == 0) ? 1 : 0;
}

__device__ __forceinline__ float gelu_exact(float x) {
    return 0.5f * x * (1.0f + erff(x * 0.70710678118654752440f));
}

// ---------------- K1: A = X(N x 67) @ W1(67 x 64) + b1 ----------------
__global__ __launch_bounds__(256) void precompute_A_kernel(
    const float* __restrict__ coords,
    const float* __restrict__ features,
    const float* __restrict__ W1,
    const float* __restrict__ b1,
    int N)
{
    __shared__ float sW1[DIN][COUT];
    __shared__ float sX[PB][XSTR];
    __shared__ float sb1[COUT];

    const int tid = threadIdx.x;
    for (int t = tid; t < DIN * COUT; t += 256) sW1[t / COUT][t % COUT] = W1[t];
    if (tid < COUT) sb1[tid] = b1[tid];

    const int base = blockIdx.x * PB;
    const int warp = tid >> 5, lane = tid & 31;

    // stage X rows: warp w stages points w*8..w*8+7
    #pragma unroll
    for (int pp = 0; pp < 8; ++pp) {
        const int p = warp * 8 + pp;
        const int n = base + p;
        if (n < N) {
            if (lane < 3) sX[p][lane] = coords[3 * n + lane];
            float2 f = *(const float2*)(features + (size_t)n * CIN + 2 * lane);
            // Destination float offset 3+2*lane is odd -> STS.64 would be
            // 4-byte aligned (HW trap). Use two scalar stores.
            sX[p][3 + 2 * lane]     = f.x;
            sX[p][3 + 2 * lane + 1] = f.y;
        }
    }
    __syncthreads();

    const int tr = tid >> 4;   // rows 4tr..4tr+3 (points)
    const int tc = tid & 15;   // cols 4tc..4tc+3 (channels)
    float acc[4][4];
    #pragma unroll
    for (int r = 0; r < 4; ++r)
        #pragma unroll
        for (int c = 0; c < 4; ++c) acc[r][c] = 0.f;

    #pragma unroll 4
    for (int kk = 0; kk < DIN; ++kk) {
        float4 b = *(const float4*)&sW1[kk][4 * tc];
        #pragma unroll
        for (int r = 0; r < 4; ++r) {
            float a = sX[4 * tr + r][kk];
            acc[r][0] += a * b.x; acc[r][1] += a * b.y;
            acc[r][2] += a * b.z; acc[r][3] += a * b.w;
        }
    }

    float4 bias = *(const float4*)&sb1[4 * tc];
    #pragma unroll
    for (int r = 0; r < 4; ++r) {
        const int n = base + 4 * tr + r;
        if (n < N) {
            float4 o = make_float4(acc[r][0] + bias.x, acc[r][1] + bias.y,
                                   acc[r][2] + bias.z, acc[r][3] + bias.w);
            *(float4*)(g_A + (size_t)n * COUT + 4 * tc) = o;
        }
    }
}

// ---------------- K2: gather + GELU + mean, fused output GEMM ----------------
// per point: hbar = mean_k gelu(A[idx[n,k]] - coords[n]@W1pos)
// out[n] = [hbar, feat_n] @ [W2; Ws] + (b2 + bs)
extern __shared__ float smem[];

__global__ __launch_bounds__(256) void gno_main_kernel(
    const float* __restrict__ coords,
    const float* __restrict__ features,
    const void*  __restrict__ idx,
    const float* __restrict__ W1,
    const float* __restrict__ W2,
    const float* __restrict__ b2,
    const float* __restrict__ Ws,
    const float* __restrict__ bs,
    float* __restrict__ out,
    int N)
{
    float* sU      = smem;                       // [HD][COUT]  128x64
    float* sHF     = sU + HD * COUT;             // [PB][HSTR]  64x132
    float* sW1pos  = sHF + PB * HSTR;            // [3][COUT]
    float* sbc     = sW1pos + 3 * COUT;          // [COUT]

    const int tid = threadIdx.x;
    for (int t = tid; t < COUT * COUT; t += 256) {
        sU[t] = W2[t];                            // rows 0..63
        sU[COUT * COUT + t] = Ws[t];              // rows 64..127
    }
    if (tid < 3 * COUT) sW1pos[tid] = W1[tid];    // first 3 rows of W1
    if (tid < COUT) sbc[tid] = b2[tid] + bs[tid];
    __syncthreads();

    const int base = blockIdx.x * PB;
    const int warp = tid >> 5, lane = tid & 31;
    const int j0 = 2 * lane;

    const bool is64 = (g_idx64 != 0);
    const long long* idx64 = (const long long*)idx;
    const int*       idx32 = (const int*)idx;

    #pragma unroll
    for (int pp = 0; pp < 8; ++pp) {
        const int p = warp * 8 + pp;
        const int n = base + p;
        if (n < N) {
            const float cx = coords[3 * n + 0];
            const float cy = coords[3 * n + 1];
            const float cz = coords[3 * n + 2];
            const float pn0 = cx * sW1pos[0 * COUT + j0] + cy * sW1pos[1 * COUT + j0] + cz * sW1pos[2 * COUT + j0];
            const float pn1 = cx * sW1pos[0 * COUT + j0 + 1] + cy * sW1pos[1 * COUT + j0 + 1] + cz * sW1pos[2 * COUT + j0 + 1];

            int mi = 0;
            if (lane < KN)
                mi = is64 ? (int)idx64[(long long)n * KN + lane]
                          : idx32[n * KN + lane];

            float h0 = 0.f, h1 = 0.f;
            #pragma unroll
            for (int kb = 0; kb < KN; kb += 8) {
                float2 a[8];
                #pragma unroll
                for (int u = 0; u < 8; ++u) {
                    int m = __shfl_sync(0xffffffffu, mi, kb + u);
                    a[u] = *(const float2*)(g_A + (size_t)m * COUT + j0);
                }
                #pragma unroll
                for (int u = 0; u < 8; ++u) {
                    h0 += gelu_exact(a[u].x - pn0);
                    h1 += gelu_exact(a[u].y - pn1);
                }
            }
            *(float2*)&sHF[p * HSTR + j0] = make_float2(h0 * (1.f / KN), h1 * (1.f / KN));
            float2 f = *(const float2*)(features + (size_t)n * CIN + j0);
            *(float2*)&sHF[p * HSTR + COUT + j0] = f;
        }
    }
    __syncthreads();

    // block GEMM: C[64 pts x 64] = sHF[64 x 128] @ sU[128 x 64]
    const int tr = tid >> 4;
    const int tc = tid & 15;
    float acc[4][4];
    #pragma unroll
    for (int r = 0; r < 4; ++r)
        #pragma unroll
        for (int c = 0; c < 4; ++c) acc[r][c] = 0.f;

    #pragma unroll 4
    for (int kk = 0; kk < HD; ++kk) {
        float4 b = *(const float4*)&sU[kk * COUT + 4 * tc];
        #pragma unroll
        for (int r = 0; r < 4; ++r) {
            float a = sHF[(4 * tr + r) * HSTR + kk];
            acc[r][0] += a * b.x; acc[r][1] += a * b.y;
            acc[r][2] += a * b.z; acc[r][3] += a * b.w;
        }
    }

    float4 bias = *(const float4*)&sbc[4 * tc];
    #pragma unroll
    for (int r = 0; r < 4; ++r) {
        const int n = base + 4 * tr + r;
        if (n < N) {
            float4 o = make_float4(acc[r][0] + bias.x, acc[r][1] + bias.y,
                                   acc[r][2] + bias.z, acc[r][3] + bias.w);
            *(float4*)(out + (size_t)n * COUT + 4 * tc) = o;
        }
    }
}

extern "C" void kernel_launch(void* const* d_in, const int* in_sizes, int n_in,
                              void* d_out, int out_size) {
    const float* coords   = (const float*)d_in[0];
    const float* features = (const float*)d_in[1];
    const void*  idx      = d_in[2];
    const float* W1 = (const float*)d_in[3];
    const float* b1 = (const float*)d_in[4];
    const float* W2 = (const float*)d_in[5];
    const float* b2 = (const float*)d_in[6];
    const float* Ws = (const float*)d_in[7];
    const float* bs = (const float*)d_in[8];
    float* out = (float*)d_out;

    int N = in_sizes[0] / 3;
    if (N > NMAX) N = NMAX;

    const int smem_bytes = (HD * COUT + PB * HSTR + 3 * COUT + COUT) * (int)sizeof(float);
    cudaFuncSetAttribute(gno_main_kernel, cudaFuncAttributeMaxDynamicSharedMemorySize, smem_bytes);

    detect_idx_kernel<<<1, 256>>>((const int*)idx);

    const int blocks = (N + PB - 1) / PB;
    precompute_A_kernel<<<blocks, 256>>>(coords, features, W1, b1, N);
    gno_main_kernel<<<blocks, 256, smem_bytes>>>(coords, features, idx, W1, W2, b2, Ws, bs, out, N);
}